// round 1
// baseline (speedup 1.0000x reference)
#include <cuda_runtime.h>
#include <math.h>

// Problem constants
#define Bc 4
#define Nn 8192
#define Mm 8192
#define Cc 512
#define Hh 8
#define Dd 64
#define SCALEF 0.125f          // D^-0.5 = 64^-0.5
#define NCHUNK 32

// ---------------- scratch (device globals: allocation-free) ----------------
__device__ float g_kfeat[(size_t)Bc * Nn * Cc];   // elu(K)+1      64 MB
__device__ float g_v[(size_t)Bc * Nn * Cc];       // V             64 MB
__device__ float g_qfeat[(size_t)Bc * Mm * Cc];   // elu(Q)+1      64 MB
__device__ float g_xatt[(size_t)Bc * Mm * Cc];    // attn output   64 MB
__device__ float g_ctx_part[(size_t)Bc * Hh * NCHUNK * Dd * Dd];  // 8 MB
__device__ float g_ksum_part[(size_t)Bc * Hh * NCHUNK * Dd];
__device__ float g_ctx[(size_t)Bc * Hh * Dd * Dd];
__device__ float g_ksum[(size_t)Bc * Hh * Dd];

__device__ __forceinline__ float elu1(float x) {
    // jax.nn.elu(x) + 1 :  x>0 ? x+1 : exp(x)
    return x > 0.0f ? x + 1.0f : expf(x);
}

// ---------------------------------------------------------------------------
// NT GEMM: out[i,j] = sum_k A[i,k] * Bw[j,k]   (K = 512 fixed)
// 128x128 tile, BK=16, 256 threads, 8x8 per thread.
// MODE 0: Ntot=1024, cols<512 -> elu1 -> g_kfeat ; cols>=512 -> g_v
// MODE 1: elu1 -> g_qfeat
// MODE 2: A = g_xatt, + bias -> out param
// ---------------------------------------------------------------------------
template <int MODE>
__global__ __launch_bounds__(256) void gemm_nt(
    const float* __restrict__ A, const float* __restrict__ Bw,
    const float* __restrict__ bias, float* __restrict__ outp)
{
    const int K = Cc;
    __shared__ float As[16][132];
    __shared__ float Bs[16][132];

    const float* Aptr = (MODE == 2) ? g_xatt : A;

    int m0 = blockIdx.y * 128;
    int n0 = blockIdx.x * 128;
    int tid = threadIdx.x;
    int ty = tid >> 4;      // 0..15
    int tx = tid & 15;      // 0..15

    float acc[8][8];
#pragma unroll
    for (int i = 0; i < 8; i++)
#pragma unroll
        for (int j = 0; j < 8; j++) acc[i][j] = 0.0f;

    for (int k0 = 0; k0 < K; k0 += 16) {
        // load 128x16 tiles of A and Bw, stored k-major (transposed) in smem
#pragma unroll
        for (int it = 0; it < 2; it++) {
            int idx = tid + it * 256;       // 0..511
            int row = idx >> 2;             // 0..127
            int c4  = idx & 3;              // 0..3
            float4 va = *(const float4*)(Aptr + (size_t)(m0 + row) * K + k0 + c4 * 4);
            As[c4 * 4 + 0][row] = va.x;
            As[c4 * 4 + 1][row] = va.y;
            As[c4 * 4 + 2][row] = va.z;
            As[c4 * 4 + 3][row] = va.w;
            float4 vb = *(const float4*)(Bw + (size_t)(n0 + row) * K + k0 + c4 * 4);
            Bs[c4 * 4 + 0][row] = vb.x;
            Bs[c4 * 4 + 1][row] = vb.y;
            Bs[c4 * 4 + 2][row] = vb.z;
            Bs[c4 * 4 + 3][row] = vb.w;
        }
        __syncthreads();

#pragma unroll
        for (int k = 0; k < 16; k++) {
            float a[8], b[8];
            *(float4*)&a[0] = *(const float4*)&As[k][ty * 8];
            *(float4*)&a[4] = *(const float4*)&As[k][ty * 8 + 4];
            *(float4*)&b[0] = *(const float4*)&Bs[k][tx * 8];
            *(float4*)&b[4] = *(const float4*)&Bs[k][tx * 8 + 4];
#pragma unroll
            for (int i = 0; i < 8; i++)
#pragma unroll
                for (int j = 0; j < 8; j++)
                    acc[i][j] = fmaf(a[i], b[j], acc[i][j]);
        }
        __syncthreads();
    }

    // epilogue
#pragma unroll
    for (int i = 0; i < 8; i++) {
        size_t row = (size_t)(m0 + ty * 8 + i);
#pragma unroll
        for (int j = 0; j < 8; j++) {
            int col = n0 + tx * 8 + j;
            float v = acc[i][j];
            if (MODE == 0) {
                if (col < Cc) g_kfeat[row * Cc + col] = elu1(v);
                else          g_v[row * Cc + (col - Cc)] = v;
            } else if (MODE == 1) {
                g_qfeat[row * Cc + col] = elu1(v);
            } else {
                outp[row * Cc + col] = v + bias[col];
            }
        }
    }
}

// ---------------------------------------------------------------------------
// ctx partial: per (b,h,chunk) accumulate 64x64 K^T V over 256 rows of N,
// plus ksum partial. Deterministic (no atomics).
// ---------------------------------------------------------------------------
__global__ __launch_bounds__(256) void ctx_partial_kernel()
{
    int chunk = blockIdx.x;           // 0..NCHUNK-1
    int bh    = blockIdx.y;           // 0..31
    int b = bh / Hh, h = bh % Hh;
    int n0 = chunk * (Nn / NCHUNK);   // 256 rows per chunk

    __shared__ float Ks[16][64];
    __shared__ float Vs[16][64];

    int tid = threadIdx.x;
    int dg = tid >> 4;   // 0..15 (d group of 4)
    int eg = tid & 15;   // 0..15 (e group of 4)

    float acc[4][4];
#pragma unroll
    for (int i = 0; i < 4; i++)
#pragma unroll
        for (int j = 0; j < 4; j++) acc[i][j] = 0.0f;
    float ks[4] = {0.0f, 0.0f, 0.0f, 0.0f};

    const float* Kbase = g_kfeat + (size_t)b * Nn * Cc + h * Dd;
    const float* Vbase = g_v     + (size_t)b * Nn * Cc + h * Dd;

    int lrow = tid >> 4;   // 0..15
    int lc4  = tid & 15;   // 0..15

    for (int r0 = 0; r0 < Nn / NCHUNK; r0 += 16) {
        size_t gro = (size_t)(n0 + r0 + lrow) * Cc + lc4 * 4;
        *(float4*)&Ks[lrow][lc4 * 4] = *(const float4*)(Kbase + gro);
        *(float4*)&Vs[lrow][lc4 * 4] = *(const float4*)(Vbase + gro);
        __syncthreads();
#pragma unroll
        for (int r = 0; r < 16; r++) {
            float4 kv = *(const float4*)&Ks[r][dg * 4];
            float4 vv = *(const float4*)&Vs[r][eg * 4];
            float kr[4] = {kv.x, kv.y, kv.z, kv.w};
            float vr[4] = {vv.x, vv.y, vv.z, vv.w};
#pragma unroll
            for (int i = 0; i < 4; i++)
#pragma unroll
                for (int j = 0; j < 4; j++)
                    acc[i][j] = fmaf(kr[i], vr[j], acc[i][j]);
            if (eg == 0) {
#pragma unroll
                for (int i = 0; i < 4; i++) ks[i] += kr[i];
            }
        }
        __syncthreads();
    }

    float* cp = g_ctx_part + ((size_t)bh * NCHUNK + chunk) * Dd * Dd;
#pragma unroll
    for (int i = 0; i < 4; i++)
#pragma unroll
        for (int j = 0; j < 4; j++)
            cp[(dg * 4 + i) * Dd + eg * 4 + j] = acc[i][j];
    if (eg == 0) {
        float* kp = g_ksum_part + ((size_t)bh * NCHUNK + chunk) * Dd;
#pragma unroll
        for (int i = 0; i < 4; i++) kp[dg * 4 + i] = ks[i];
    }
}

__global__ __launch_bounds__(256) void ctx_reduce_kernel()
{
    int bh = blockIdx.x;
    int tid = threadIdx.x;
    for (int i = tid; i < Dd * Dd; i += 256) {
        float s = 0.0f;
#pragma unroll 4
        for (int c = 0; c < NCHUNK; c++)
            s += g_ctx_part[((size_t)bh * NCHUNK + c) * Dd * Dd + i];
        g_ctx[(size_t)bh * Dd * Dd + i] = s;
    }
    if (tid < Dd) {
        float s = 0.0f;
#pragma unroll 4
        for (int c = 0; c < NCHUNK; c++)
            s += g_ksum_part[((size_t)bh * NCHUNK + c) * Dd + tid];
        g_ksum[(size_t)bh * Dd + tid] = s;
    }
}

// ---------------------------------------------------------------------------
// x = (qfeat @ ctx) * SCALE / (1e-6 + qfeat . ksum), per (b,h), 64-row tiles.
// ---------------------------------------------------------------------------
__global__ __launch_bounds__(256) void attn_apply_kernel()
{
    int bh = blockIdx.y;
    int b = bh / Hh, h = bh % Hh;
    int m0 = blockIdx.x * 64;

    __shared__ float Cs[64][64];     // ctx[d][e]
    __shared__ float Qs[64][64];     // qfeat[row][d]
    __shared__ float ksum_s[64];
    __shared__ float pden[64][4];
    __shared__ float den[64];        // SCALE / (1e-6 + denom)

    int tid = threadIdx.x;

    // load ctx (4096 floats)
    {
        const float4* src = (const float4*)(g_ctx + (size_t)bh * Dd * Dd);
        float4* dst = (float4*)&Cs[0][0];
        for (int i = tid; i < 1024; i += 256) dst[i] = src[i];
    }
    if (tid < 64) ksum_s[tid] = g_ksum[(size_t)bh * Dd + tid];

    // load Q tile (64 rows x 64 d)
    for (int i = tid; i < 1024; i += 256) {
        int row = i >> 4;
        int c4  = i & 15;
        *(float4*)&Qs[row][c4 * 4] =
            *(const float4*)(g_qfeat + ((size_t)b * Mm + m0 + row) * Cc + h * Dd + c4 * 4);
    }
    __syncthreads();

    // denominators: thread (row, quarter)
    {
        int row = tid >> 2;
        int qq  = tid & 3;
        float s = 0.0f;
#pragma unroll
        for (int d4 = 0; d4 < 4; d4++) {
            float4 qv = *(const float4*)&Qs[row][qq * 16 + d4 * 4];
            float4 kv = *(const float4*)&ksum_s[qq * 16 + d4 * 4];
            s += qv.x * kv.x + qv.y * kv.y + qv.z * kv.z + qv.w * kv.w;
        }
        pden[row][qq] = s;
    }
    __syncthreads();
    if (tid < 64) {
        float d0 = pden[tid][0] + pden[tid][1] + pden[tid][2] + pden[tid][3];
        den[tid] = SCALEF / (1e-6f + d0);
    }
    __syncthreads();

    int rg = tid >> 4;   // row group (4 rows)
    int eg = tid & 15;   // e group (4 cols)

    float acc[4][4];
#pragma unroll
    for (int i = 0; i < 4; i++)
#pragma unroll
        for (int j = 0; j < 4; j++) acc[i][j] = 0.0f;

#pragma unroll 4
    for (int d = 0; d < 64; d++) {
        float4 cv = *(const float4*)&Cs[d][eg * 4];
        float q0 = Qs[rg * 4 + 0][d];
        float q1 = Qs[rg * 4 + 1][d];
        float q2 = Qs[rg * 4 + 2][d];
        float q3 = Qs[rg * 4 + 3][d];
        acc[0][0] = fmaf(q0, cv.x, acc[0][0]); acc[0][1] = fmaf(q0, cv.y, acc[0][1]);
        acc[0][2] = fmaf(q0, cv.z, acc[0][2]); acc[0][3] = fmaf(q0, cv.w, acc[0][3]);
        acc[1][0] = fmaf(q1, cv.x, acc[1][0]); acc[1][1] = fmaf(q1, cv.y, acc[1][1]);
        acc[1][2] = fmaf(q1, cv.z, acc[1][2]); acc[1][3] = fmaf(q1, cv.w, acc[1][3]);
        acc[2][0] = fmaf(q2, cv.x, acc[2][0]); acc[2][1] = fmaf(q2, cv.y, acc[2][1]);
        acc[2][2] = fmaf(q2, cv.z, acc[2][2]); acc[2][3] = fmaf(q2, cv.w, acc[2][3]);
        acc[3][0] = fmaf(q3, cv.x, acc[3][0]); acc[3][1] = fmaf(q3, cv.y, acc[3][1]);
        acc[3][2] = fmaf(q3, cv.z, acc[3][2]); acc[3][3] = fmaf(q3, cv.w, acc[3][3]);
    }

#pragma unroll
    for (int i = 0; i < 4; i++) {
        float dv = den[rg * 4 + i];
        float4 o;
        o.x = acc[i][0] * dv;
        o.y = acc[i][1] * dv;
        o.z = acc[i][2] * dv;
        o.w = acc[i][3] * dv;
        *(float4*)(g_xatt + ((size_t)b * Mm + m0 + rg * 4 + i) * Cc + h * Dd + eg * 4) = o;
    }
}

// ---------------------------------------------------------------------------
extern "C" void kernel_launch(void* const* d_in, const int* in_sizes, int n_in,
                              void* d_out, int out_size)
{
    const float* target = (const float*)d_in[0];   // [B,M,C]
    const float* refer  = (const float*)d_in[1];   // [B,N,C]
    const float* q_w    = (const float*)d_in[2];   // [C,C]
    const float* kv_w   = (const float*)d_in[3];   // [2C,C]
    const float* proj_w = (const float*)d_in[4];   // [C,C]
    const float* proj_b = (const float*)d_in[5];   // [C]
    float* out = (float*)d_out;

    // 1) kv projection + elu on K half (fused)
    gemm_nt<0><<<dim3((2 * Cc) / 128, (Bc * Nn) / 128), 256>>>(refer, kv_w, nullptr, nullptr);
    // 2) ctx + ksum (deterministic 2-stage reduction)
    ctx_partial_kernel<<<dim3(NCHUNK, Bc * Hh), 256>>>();
    ctx_reduce_kernel<<<Bc * Hh, 256>>>();
    // 3) q projection + elu (fused)
    gemm_nt<1><<<dim3(Cc / 128, (Bc * Mm) / 128), 256>>>(target, q_w, nullptr, nullptr);
    // 4) attention apply (q@ctx, denom, scale/divide)
    attn_apply_kernel<<<dim3(Mm / 64, Bc * Hh), 256>>>();
    // 5) output projection + bias
    gemm_nt<2><<<dim3(Cc / 128, (Bc * Mm) / 128), 256>>>(nullptr, proj_w, proj_b, out);
}

// round 5
// speedup vs baseline: 2.0250x; 2.0250x over previous
#include <cuda_runtime.h>
#include <cuda_bf16.h>
#include <math.h>
#include <stdint.h>

// Problem constants
#define Bc 4
#define Nn 8192
#define Mm 8192
#define Cc 512
#define Hh 8
#define Dd 64
#define SCALEF 0.125f          // D^-0.5
#define NCHUNK 32

// ---------------- scratch (device globals: allocation-free) ----------------
__device__ float g_kfeat[(size_t)Bc * Nn * Cc];
__device__ float g_v[(size_t)Bc * Nn * Cc];
__device__ float g_qfeat[(size_t)Bc * Mm * Cc];
__device__ float g_xatt[(size_t)Bc * Mm * Cc];
__device__ float g_ctx_part[(size_t)Bc * Hh * NCHUNK * Dd * Dd];
__device__ float g_ksum_part[(size_t)Bc * Hh * NCHUNK * Dd];
__device__ float g_ctx[(size_t)Bc * Hh * Dd * Dd];
__device__ float g_ksum[(size_t)Bc * Hh * Dd];

__device__ __forceinline__ float elu1(float x) {
    return x > 0.0f ? x + 1.0f : expf(x);
}

__device__ __forceinline__ uint32_t smem_to_u32(const void* p) {
    uint32_t a;
    asm("{ .reg .u64 t; cvta.to.shared.u64 t, %1; cvt.u32.u64 %0, t; }"
        : "=r"(a) : "l"(p));
    return a;
}

// ldmatrix helpers (baseline PTX — compiles for plain sm_103 target)
__device__ __forceinline__ void ldsm_x4(uint32_t* r, uint32_t addr) {
    asm volatile("ldmatrix.sync.aligned.m8n8.x4.shared.b16 {%0,%1,%2,%3}, [%4];"
                 : "=r"(r[0]), "=r"(r[1]), "=r"(r[2]), "=r"(r[3]) : "r"(addr));
}
__device__ __forceinline__ void ldsm_x2(uint32_t* r, uint32_t addr) {
    asm volatile("ldmatrix.sync.aligned.m8n8.x2.shared.b16 {%0,%1}, [%2];"
                 : "=r"(r[0]), "=r"(r[1]) : "r"(addr));
}

// mma.sync m16n8k16 bf16 -> fp32 accum
__device__ __forceinline__ void mma_bf16(float* c, const uint32_t* a, const uint32_t* b) {
    asm volatile(
        "mma.sync.aligned.m16n8k16.row.col.f32.bf16.bf16.f32 "
        "{%0,%1,%2,%3}, {%4,%5,%6,%7}, {%8,%9}, {%0,%1,%2,%3};"
        : "+f"(c[0]), "+f"(c[1]), "+f"(c[2]), "+f"(c[3])
        : "r"(a[0]), "r"(a[1]), "r"(a[2]), "r"(a[3]), "r"(b[0]), "r"(b[1]));
}

// ---------------- SMEM layout for GEMM (bytes) ------------------------------
// 4 tiles of [128 rows][72 bf16] (BK=64 used, 8 pad). Row pitch 144 B.
#define TPITCH   144
#define T_A_HI   0
#define T_A_LO   18432
#define T_B_HI   36864
#define T_B_LO   55296
#define GEMM_SMEM 73728

// split fp32 -> (hi,lo) bf16, store 4 cols (8 B each tile) row-major padded
__device__ __forceinline__ void split_store(char* smem, int off_hi, int off_lo,
                                            int row, int c4, float4 v) {
    float xs[4] = {v.x, v.y, v.z, v.w};
    __nv_bfloat16 hi[4], lo[4];
#pragma unroll
    for (int j = 0; j < 4; j++) {
        hi[j] = __float2bfloat16(xs[j]);
        lo[j] = __float2bfloat16(xs[j] - __bfloat162float(hi[j]));
    }
    uint32_t bo = (uint32_t)row * TPITCH + (uint32_t)c4 * 8;
    *(__nv_bfloat162*)(smem + off_hi + bo)     = __halves2bfloat162(hi[0], hi[1]);
    *(__nv_bfloat162*)(smem + off_hi + bo + 4) = __halves2bfloat162(hi[2], hi[3]);
    *(__nv_bfloat162*)(smem + off_lo + bo)     = __halves2bfloat162(lo[0], lo[1]);
    *(__nv_bfloat162*)(smem + off_lo + bo + 4) = __halves2bfloat162(lo[2], lo[3]);
}

// ---------------------------------------------------------------------------
// HMMA NT GEMM: out[i,j] = sum_k A[i,k]*Bw[j,k], K=512, tile 128x128, BK=64.
// bf16 2-term split: hi*hi + hi*lo + lo*hi (fp32 accum) ~= fp32 GEMM (4e-6).
// MODE 0: col<512 -> elu1 -> g_kfeat ; col>=512 -> g_v
// MODE 1: elu1 -> g_qfeat
// MODE 2: A = g_xatt, + bias -> outp
// ---------------------------------------------------------------------------
template <int MODE>
__global__ __launch_bounds__(256) void gemm_mma(
    const float* __restrict__ A, const float* __restrict__ Bw,
    const float* __restrict__ bias, float* __restrict__ outp)
{
    extern __shared__ char smem[];
    const uint32_t sb = smem_to_u32(smem);
    const int tid  = threadIdx.x;
    const int wid  = tid >> 5;
    const int lane = tid & 31;
    const int warp_m = wid & 3;     // 0..3  (32 rows each)
    const int warp_n = wid >> 2;    // 0..1  (64 cols each)

    const float* Aptr = (MODE == 2) ? g_xatt : A;
    const int m0 = blockIdx.y * 128;
    const int n0 = blockIdx.x * 128;

    // ldmatrix lane address components
    const int aq = lane >> 3, ar = lane & 7;
    const int a_row_base = warp_m * 32 + (aq & 1) * 8 + ar;   // + mt*16
    const int a_colb     = ((aq >> 1) * 8) * 2;               // bytes, + k16*32
    const int br  = lane & 7;
    const int bhf = (lane >> 3) & 1;
    const int b_row_base = warp_n * 64 + br;                  // + nt*8
    const int b_colb     = (bhf * 8) * 2;                     // bytes, + k16*32

    float acc[2][8][4];
#pragma unroll
    for (int mt = 0; mt < 2; mt++)
#pragma unroll
        for (int nt = 0; nt < 8; nt++)
#pragma unroll
            for (int e = 0; e < 4; e++) acc[mt][nt][e] = 0.0f;

    for (int chunk = 0; chunk < 8; chunk++) {
        const int k0 = chunk * 64;
        __syncthreads();   // previous chunk's compute done before overwrite
        // load + split-convert A and B chunks [128 x 64] fp32 each
#pragma unroll
        for (int it = 0; it < 8; it++) {
            int idx = tid + it * 256;
            int row = idx >> 4, c4 = idx & 15;
            float4 va = *(const float4*)(Aptr + (size_t)(m0 + row) * Cc + k0 + c4 * 4);
            split_store(smem, T_A_HI, T_A_LO, row, c4, va);
            float4 vb = *(const float4*)(Bw + (size_t)(n0 + row) * Cc + k0 + c4 * 4);
            split_store(smem, T_B_HI, T_B_LO, row, c4, vb);
        }
        __syncthreads();

#pragma unroll
        for (int k16 = 0; k16 < 4; k16++) {
            const uint32_t koff = (uint32_t)k16 * 32;   // 16 bf16 = 32 bytes
            uint32_t bh[8][2], bl[8][2];
#pragma unroll
            for (int nt = 0; nt < 8; nt++) {
                uint32_t boff = (uint32_t)(b_row_base + nt * 8) * TPITCH + b_colb + koff;
                ldsm_x2(bh[nt], sb + T_B_HI + boff);
                ldsm_x2(bl[nt], sb + T_B_LO + boff);
            }
#pragma unroll
            for (int mt = 0; mt < 2; mt++) {
                uint32_t aoff = (uint32_t)(a_row_base + mt * 16) * TPITCH + a_colb + koff;
                uint32_t ah[4], al[4];
                ldsm_x4(ah, sb + T_A_HI + aoff);
                ldsm_x4(al, sb + T_A_LO + aoff);
#pragma unroll
                for (int nt = 0; nt < 8; nt++) {
                    mma_bf16(acc[mt][nt], ah, bh[nt]);
                    mma_bf16(acc[mt][nt], ah, bl[nt]);
                    mma_bf16(acc[mt][nt], al, bh[nt]);
                }
            }
        }
    }

    // ---- epilogue: fragment registers -> gmem (float2 per thread-half) ----
    const int tr = lane >> 2;          // 0..7
    const int tc = (lane & 3) * 2;     // 0,2,4,6
    const bool khalf = (MODE == 0) && (n0 < Cc);

#pragma unroll
    for (int mt = 0; mt < 2; mt++) {
#pragma unroll
        for (int nt = 0; nt < 8; nt++) {
#pragma unroll
            for (int half = 0; half < 2; half++) {
                size_t row = (size_t)(m0 + warp_m * 32 + mt * 16 + tr + half * 8);
                int col = n0 + warp_n * 64 + nt * 8 + tc;
                float v0 = acc[mt][nt][half * 2 + 0];
                float v1 = acc[mt][nt][half * 2 + 1];
                if (MODE == 0) {
                    if (khalf) {
                        *(float2*)(g_kfeat + row * Cc + col) =
                            make_float2(elu1(v0), elu1(v1));
                    } else {
                        *(float2*)(g_v + row * Cc + (col - Cc)) = make_float2(v0, v1);
                    }
                } else if (MODE == 1) {
                    *(float2*)(g_qfeat + row * Cc + col) =
                        make_float2(elu1(v0), elu1(v1));
                } else {
                    *(float2*)(outp + row * Cc + col) =
                        make_float2(v0 + __ldg(bias + col), v1 + __ldg(bias + col + 1));
                }
            }
        }
    }
}

// ---------------------------------------------------------------------------
// ctx partial: per (b,h,chunk) 64x64 K^T V over 256 N-rows + ksum partial.
// ---------------------------------------------------------------------------
__global__ __launch_bounds__(256) void ctx_partial_kernel()
{
    int chunk = blockIdx.x;
    int bh    = blockIdx.y;
    int b = bh / Hh, h = bh % Hh;
    int n0 = chunk * (Nn / NCHUNK);

    __shared__ float Ks[16][64];
    __shared__ float Vs[16][64];

    int tid = threadIdx.x;
    int dg = tid >> 4;
    int eg = tid & 15;

    float acc[4][4];
#pragma unroll
    for (int i = 0; i < 4; i++)
#pragma unroll
        for (int j = 0; j < 4; j++) acc[i][j] = 0.0f;
    float ks[4] = {0.0f, 0.0f, 0.0f, 0.0f};

    const float* Kbase = g_kfeat + (size_t)b * Nn * Cc + h * Dd;
    const float* Vbase = g_v     + (size_t)b * Nn * Cc + h * Dd;

    int lrow = tid >> 4;
    int lc4  = tid & 15;

    for (int r0 = 0; r0 < Nn / NCHUNK; r0 += 16) {
        size_t gro = (size_t)(n0 + r0 + lrow) * Cc + lc4 * 4;
        *(float4*)&Ks[lrow][lc4 * 4] = *(const float4*)(Kbase + gro);
        *(float4*)&Vs[lrow][lc4 * 4] = *(const float4*)(Vbase + gro);
        __syncthreads();
#pragma unroll
        for (int r = 0; r < 16; r++) {
            float4 kv = *(const float4*)&Ks[r][dg * 4];
            float4 vv = *(const float4*)&Vs[r][eg * 4];
            float kr[4] = {kv.x, kv.y, kv.z, kv.w};
            float vr[4] = {vv.x, vv.y, vv.z, vv.w};
#pragma unroll
            for (int i = 0; i < 4; i++)
#pragma unroll
                for (int j = 0; j < 4; j++)
                    acc[i][j] = fmaf(kr[i], vr[j], acc[i][j]);
            if (eg == 0) {
#pragma unroll
                for (int i = 0; i < 4; i++) ks[i] += kr[i];
            }
        }
        __syncthreads();
    }

    float* cp = g_ctx_part + ((size_t)bh * NCHUNK + chunk) * Dd * Dd;
#pragma unroll
    for (int i = 0; i < 4; i++)
#pragma unroll
        for (int j = 0; j < 4; j++)
            cp[(dg * 4 + i) * Dd + eg * 4 + j] = acc[i][j];
    if (eg == 0) {
        float* kp = g_ksum_part + ((size_t)bh * NCHUNK + chunk) * Dd;
#pragma unroll
        for (int i = 0; i < 4; i++) kp[dg * 4 + i] = ks[i];
    }
}

__global__ __launch_bounds__(256) void ctx_reduce_kernel()
{
    int bh = blockIdx.x;
    int tid = threadIdx.x;
    for (int i = tid; i < Dd * Dd; i += 256) {
        float s = 0.0f;
#pragma unroll 4
        for (int c = 0; c < NCHUNK; c++)
            s += g_ctx_part[((size_t)bh * NCHUNK + c) * Dd * Dd + i];
        g_ctx[(size_t)bh * Dd * Dd + i] = s;
    }
    if (tid < Dd) {
        float s = 0.0f;
#pragma unroll 4
        for (int c = 0; c < NCHUNK; c++)
            s += g_ksum_part[((size_t)bh * NCHUNK + c) * Dd + tid];
        g_ksum[(size_t)bh * Dd + tid] = s;
    }
}

// ---------------------------------------------------------------------------
// x = (qfeat @ ctx) * SCALE / (1e-6 + qfeat . ksum)
// ---------------------------------------------------------------------------
__global__ __launch_bounds__(256) void attn_apply_kernel()
{
    int bh = blockIdx.y;
    int b = bh / Hh, h = bh % Hh;
    int m0 = blockIdx.x * 64;

    __shared__ float Cs[64][64];
    __shared__ float Qs[64][64];
    __shared__ float ksum_s[64];
    __shared__ float pden[64][4];
    __shared__ float den[64];

    int tid = threadIdx.x;

    {
        const float4* src = (const float4*)(g_ctx + (size_t)bh * Dd * Dd);
        float4* dst = (float4*)&Cs[0][0];
        for (int i = tid; i < 1024; i += 256) dst[i] = src[i];
    }
    if (tid < 64) ksum_s[tid] = g_ksum[(size_t)bh * Dd + tid];

    for (int i = tid; i < 1024; i += 256) {
        int row = i >> 4;
        int c4  = i & 15;
        *(float4*)&Qs[row][c4 * 4] =
            *(const float4*)(g_qfeat + ((size_t)b * Mm + m0 + row) * Cc + h * Dd + c4 * 4);
    }
    __syncthreads();

    {
        int row = tid >> 2;
        int qq  = tid & 3;
        float s = 0.0f;
#pragma unroll
        for (int d4 = 0; d4 < 4; d4++) {
            float4 qv = *(const float4*)&Qs[row][qq * 16 + d4 * 4];
            float4 kv = *(const float4*)&ksum_s[qq * 16 + d4 * 4];
            s += qv.x * kv.x + qv.y * kv.y + qv.z * kv.z + qv.w * kv.w;
        }
        pden[row][qq] = s;
    }
    __syncthreads();
    if (tid < 64) {
        float d0 = pden[tid][0] + pden[tid][1] + pden[tid][2] + pden[tid][3];
        den[tid] = SCALEF / (1e-6f + d0);
    }
    __syncthreads();

    int rg = tid >> 4;
    int eg = tid & 15;

    float acc[4][4];
#pragma unroll
    for (int i = 0; i < 4; i++)
#pragma unroll
        for (int j = 0; j < 4; j++) acc[i][j] = 0.0f;

#pragma unroll 4
    for (int d = 0; d < 64; d++) {
        float4 cv = *(const float4*)&Cs[d][eg * 4];
        float q0 = Qs[rg * 4 + 0][d];
        float q1 = Qs[rg * 4 + 1][d];
        float q2 = Qs[rg * 4 + 2][d];
        float q3 = Qs[rg * 4 + 3][d];
        acc[0][0] = fmaf(q0, cv.x, acc[0][0]); acc[0][1] = fmaf(q0, cv.y, acc[0][1]);
        acc[0][2] = fmaf(q0, cv.z, acc[0][2]); acc[0][3] = fmaf(q0, cv.w, acc[0][3]);
        acc[1][0] = fmaf(q1, cv.x, acc[1][0]); acc[1][1] = fmaf(q1, cv.y, acc[1][1]);
        acc[1][2] = fmaf(q1, cv.z, acc[1][2]); acc[1][3] = fmaf(q1, cv.w, acc[1][3]);
        acc[2][0] = fmaf(q2, cv.x, acc[2][0]); acc[2][1] = fmaf(q2, cv.y, acc[2][1]);
        acc[2][2] = fmaf(q2, cv.z, acc[2][2]); acc[2][3] = fmaf(q2, cv.w, acc[2][3]);
        acc[3][0] = fmaf(q3, cv.x, acc[3][0]); acc[3][1] = fmaf(q3, cv.y, acc[3][1]);
        acc[3][2] = fmaf(q3, cv.z, acc[3][2]); acc[3][3] = fmaf(q3, cv.w, acc[3][3]);
    }

#pragma unroll
    for (int i = 0; i < 4; i++) {
        float dv = den[rg * 4 + i];
        float4 o;
        o.x = acc[i][0] * dv;
        o.y = acc[i][1] * dv;
        o.z = acc[i][2] * dv;
        o.w = acc[i][3] * dv;
        *(float4*)(g_xatt + ((size_t)b * Mm + m0 + rg * 4 + i) * Cc + h * Dd + eg * 4) = o;
    }
}

// ---------------------------------------------------------------------------
extern "C" void kernel_launch(void* const* d_in, const int* in_sizes, int n_in,
                              void* d_out, int out_size)
{
    const float* target = (const float*)d_in[0];
    const float* refer  = (const float*)d_in[1];
    const float* q_w    = (const float*)d_in[2];
    const float* kv_w   = (const float*)d_in[3];
    const float* proj_w = (const float*)d_in[4];
    const float* proj_b = (const float*)d_in[5];
    float* out = (float*)d_out;

    // Unconditional (idempotent, deterministic — no static guards allowed)
    cudaFuncSetAttribute(gemm_mma<0>, cudaFuncAttributeMaxDynamicSharedMemorySize, GEMM_SMEM);
    cudaFuncSetAttribute(gemm_mma<1>, cudaFuncAttributeMaxDynamicSharedMemorySize, GEMM_SMEM);
    cudaFuncSetAttribute(gemm_mma<2>, cudaFuncAttributeMaxDynamicSharedMemorySize, GEMM_SMEM);

    // 1) kv projection + elu on K half (HMMA split-bf16)
    gemm_mma<0><<<dim3((2 * Cc) / 128, (Bc * Nn) / 128), 256, GEMM_SMEM>>>(refer, kv_w, nullptr, nullptr);
    // 2) ctx + ksum
    ctx_partial_kernel<<<dim3(NCHUNK, Bc * Hh), 256>>>();
    ctx_reduce_kernel<<<Bc * Hh, 256>>>();
    // 3) q projection + elu
    gemm_mma<1><<<dim3(Cc / 128, (Bc * Mm) / 128), 256, GEMM_SMEM>>>(target, q_w, nullptr, nullptr);
    // 4) attention apply
    attn_apply_kernel<<<dim3(Mm / 64, Bc * Hh), 256>>>();
    // 5) output projection + bias
    gemm_mma<2><<<dim3(Cc / 128, (Bc * Mm) / 128), 256, GEMM_SMEM>>>(nullptr, proj_w, proj_b, out);
}